// round 6
// baseline (speedup 1.0000x reference)
#include <cuda_runtime.h>

// ---------------- problem constants ----------------
#define N_NODES 50000
#define N_EDGES 800000
#define ET      (N_EDGES + N_NODES)   // edges + self loops
#define IN_CH   128
#define HEADS   4
#define C_CH    64
#define HC      256                    // HEADS * C_CH
#define NEG_SLOPE 0.2f

// ---------------- device scratch (static, no allocation) ----------------
// NOTE: these are ONLY ever referenced from device code. Passing a __device__
// symbol from host code yields the host shadow address (and on GB300 the
// write is silently absorbed via ATS) — that was the R4 bug.
__device__ __align__(16) float g_xl[(size_t)N_NODES * HC];       // projected features
__device__ __align__(16) float g_asrc[N_NODES * HEADS];
__device__ __align__(16) float g_adst[N_NODES * HEADS];
__device__ __align__(16) float g_amax[N_NODES * HEADS];
__device__ __align__(16) float g_denom[N_NODES * HEADS];
__device__ __align__(16) float g_ealpha[(size_t)ET * HEADS];     // edge scores -> exp values

// ---------------- K1: xl = x @ W^T  (tiled fp32 GEMM, writes g_xl directly) ----
#define BM 64
#define BN 64
#define BK 16
__global__ void k_gemm(const float* __restrict__ A,
                       const float* __restrict__ Wm) {
    __shared__ float As[BK][BM];
    __shared__ float Bs[BK][BN];
    const int bm = blockIdx.y * BM;
    const int bn = blockIdx.x * BN;
    const int tid = threadIdx.x;            // 256 threads
    const int tx = tid & 15;
    const int ty = tid >> 4;

    float acc[4][4] = {};

    for (int kk = 0; kk < IN_CH; kk += BK) {
        // load A tile (64 x 16)
        #pragma unroll
        for (int i = tid; i < BM * BK; i += 256) {
            int m = i / BK, k = i % BK;
            int row = bm + m;
            As[k][m] = (row < N_NODES) ? A[(size_t)row * IN_CH + kk + k] : 0.f;
        }
        // load W tile (64 x 16); W is [256][128] row-major, bn+n < 256 always
        #pragma unroll
        for (int i = tid; i < BN * BK; i += 256) {
            int n = i / BK, k = i % BK;
            Bs[k][n] = Wm[(size_t)(bn + n) * IN_CH + kk + k];
        }
        __syncthreads();

        #pragma unroll
        for (int k = 0; k < BK; k++) {
            float a[4], b[4];
            #pragma unroll
            for (int i = 0; i < 4; i++) a[i] = As[k][ty * 4 + i];
            #pragma unroll
            for (int j = 0; j < 4; j++) b[j] = Bs[k][tx * 4 + j];
            #pragma unroll
            for (int i = 0; i < 4; i++)
                #pragma unroll
                for (int j = 0; j < 4; j++)
                    acc[i][j] += a[i] * b[j];
        }
        __syncthreads();
    }

    #pragma unroll
    for (int i = 0; i < 4; i++) {
        int row = bm + ty * 4 + i;
        if (row >= N_NODES) continue;
        #pragma unroll
        for (int j = 0; j < 4; j++)
            g_xl[(size_t)row * HC + bn + tx * 4 + j] = acc[i][j];
    }
}

// ---------------- K2: per-node attention logits ----------------
// one warp per node; lane l covers channels [8l, 8l+8), head = l/8
__global__ void k_logits(const float* __restrict__ att_src,
                         const float* __restrict__ att_dst) {
    int warp = (blockIdx.x * blockDim.x + threadIdx.x) >> 5;
    int lane = threadIdx.x & 31;
    if (warp >= N_NODES) return;
    int col = lane * 8;
    int h = lane >> 3;
    const float* xr = g_xl + (size_t)warp * HC + col;
    float ss = 0.f, sd = 0.f;
    #pragma unroll
    for (int j = 0; j < 8; j++) {
        float v = xr[j];
        ss += v * att_src[col + j];   // att layout [H][C] flattened == channel index
        sd += v * att_dst[col + j];
    }
    #pragma unroll
    for (int off = 4; off >= 1; off >>= 1) {
        ss += __shfl_down_sync(0xffffffff, ss, off);
        sd += __shfl_down_sync(0xffffffff, sd, off);
    }
    if ((lane & 7) == 0) {
        g_asrc[warp * HEADS + h] = ss;
        g_adst[warp * HEADS + h] = sd;
    }
}

// ---------------- K3: init (out=0, amax=-inf, denom=0) ----------------
__global__ void k_init(float* __restrict__ out) {
    int i = blockIdx.x * blockDim.x + threadIdx.x;
    if (i < N_NODES * HC) out[i] = 0.f;
    if (i < N_NODES * HEADS) { g_amax[i] = -1e30f; g_denom[i] = 0.f; }
}

// float atomic max via signed-int / unsigned-int monotonicity trick
__device__ __forceinline__ void atomicMaxF(float* addr, float v) {
    if (v >= 0.f) atomicMax((int*)addr, __float_as_int(v));
    else          atomicMin((unsigned int*)addr, __float_as_uint(v));
}

// ---------------- K4: edge scores + segment max ----------------
__global__ void k_edge_max(const int* __restrict__ ei) {
    int e = blockIdx.x * blockDim.x + threadIdx.x;
    if (e >= ET) return;
    int s, d;
    if (e < N_EDGES) { s = ei[e]; d = ei[N_EDGES + e]; }
    else             { s = d = e - N_EDGES; }
    const float4 as = *(const float4*)(g_asrc + s * 4);
    const float4 ad = *(const float4*)(g_adst + d * 4);
    float al[4] = { as.x + ad.x, as.y + ad.y, as.z + ad.z, as.w + ad.w };
    float* ep = g_ealpha + (size_t)e * 4;
    #pragma unroll
    for (int h = 0; h < 4; h++) {
        float a = al[h];
        a = (a > 0.f) ? a : NEG_SLOPE * a;   // leaky relu
        ep[h] = a;
        atomicMaxF(&g_amax[d * 4 + h], a);
    }
}

// ---------------- K5: exp + segment sum ----------------
__global__ void k_edge_exp(const int* __restrict__ ei) {
    int e = blockIdx.x * blockDim.x + threadIdx.x;
    if (e >= ET) return;
    int d = (e < N_EDGES) ? ei[N_EDGES + e] : (e - N_EDGES);
    float4 al = *(float4*)(g_ealpha + (size_t)e * 4);
    const float4 mx = *(const float4*)(g_amax + d * 4);
    float e0 = __expf(al.x - mx.x);
    float e1 = __expf(al.y - mx.y);
    float e2 = __expf(al.z - mx.z);
    float e3 = __expf(al.w - mx.w);
    *(float4*)(g_ealpha + (size_t)e * 4) = make_float4(e0, e1, e2, e3);
    asm volatile("red.global.add.v4.f32 [%0], {%1,%2,%3,%4};"
                 :: "l"(g_denom + d * 4), "f"(e0), "f"(e1), "f"(e2), "f"(e3)
                 : "memory");
}

// ---------------- K6: weighted scatter-aggregate ----------------
// one warp per edge; lane l handles channels [8l, 8l+8), head = l/8
__global__ void k_aggregate(const int* __restrict__ ei,
                            float* __restrict__ out) {
    int gw = (blockIdx.x * blockDim.x + threadIdx.x) >> 5;
    int lane = threadIdx.x & 31;
    if (gw >= ET) return;
    int s, d;
    if (gw < N_EDGES) { s = ei[gw]; d = ei[N_EDGES + gw]; }
    else              { s = d = gw - N_EDGES; }
    int h = lane >> 3;
    float coef = g_ealpha[(size_t)gw * 4 + h] / g_denom[d * 4 + h];
    const float4* xs = (const float4*)(g_xl + (size_t)s * HC) + lane * 2;
    float4 v0 = xs[0];
    float4 v1 = xs[1];
    float* op = out + (size_t)d * HC + lane * 8;
    asm volatile("red.global.add.v4.f32 [%0], {%1,%2,%3,%4};"
                 :: "l"(op), "f"(v0.x * coef), "f"(v0.y * coef),
                    "f"(v0.z * coef), "f"(v0.w * coef) : "memory");
    asm volatile("red.global.add.v4.f32 [%0], {%1,%2,%3,%4};"
                 :: "l"(op + 4), "f"(v1.x * coef), "f"(v1.y * coef),
                    "f"(v1.z * coef), "f"(v1.w * coef) : "memory");
}

// ---------------- K7: bias + ELU ----------------
__global__ void k_finish(float* __restrict__ out, const float* __restrict__ bias) {
    int i = blockIdx.x * blockDim.x + threadIdx.x;
    if (i >= N_NODES * HC) return;
    float v = out[i] + bias[i & (HC - 1)];
    out[i] = (v > 0.f) ? v : (expf(v) - 1.f);
}

// ---------------- launch ----------------
extern "C" void kernel_launch(void* const* d_in, const int* in_sizes, int n_in,
                              void* d_out, int out_size) {
    const float* x       = (const float*)d_in[0];
    const int*   ei      = (const int*)d_in[1];   // int32 (JAX x64 disabled demotes int64)
    const float* Wm      = (const float*)d_in[2];
    const float* att_src = (const float*)d_in[3];
    const float* att_dst = (const float*)d_in[4];
    const float* bias    = (const float*)d_in[5];
    float*       out     = (float*)d_out;

    // K1: projection GEMM (writes g_xl via device symbol)
    dim3 ggrid(HC / BN, (N_NODES + BM - 1) / BM);
    k_gemm<<<ggrid, 256>>>(x, Wm);

    // K2: per-node logits (1 warp/node)
    k_logits<<<(N_NODES * 32 + 255) / 256, 256>>>(att_src, att_dst);

    // K3: init out / amax / denom
    k_init<<<(N_NODES * HC + 255) / 256, 256>>>(out);

    // K4: edge scores + segment max
    k_edge_max<<<(ET + 255) / 256, 256>>>(ei);

    // K5: exp + segment sum
    k_edge_exp<<<(ET + 255) / 256, 256>>>(ei);

    // K6: scatter aggregate (1 warp/edge)
    k_aggregate<<<((size_t)ET * 32 + 255) / 256, 256>>>(ei, out);

    // K7: bias + ELU
    k_finish<<<(N_NODES * HC + 255) / 256, 256>>>(out, bias);
}

// round 7
// speedup vs baseline: 1.7851x; 1.7851x over previous
#include <cuda_runtime.h>

// ---------------- problem constants ----------------
#define N_NODES 50000
#define N_EDGES 800000
#define ET      (N_EDGES + N_NODES)   // edges + self loops
#define IN_CH   128
#define HEADS   4
#define C_CH    64
#define HC      256                    // HEADS * C_CH
#define NEG_SLOPE 0.2f
#define NB_SCAN 98                     // ceil(50000/512)

// ---------------- device scratch (device-side refs only) ----------------
__device__ __align__(16) float g_xl[(size_t)N_NODES * HC];   // projected features
__device__ __align__(16) float g_asrc[N_NODES * HEADS];
__device__ __align__(16) float g_adst[N_NODES * HEADS];
__device__ int g_deg[N_NODES];
__device__ int g_rowptr[N_NODES + 1];
__device__ int g_cursor[N_NODES];
__device__ int g_blocksum[128];
__device__ int g_blockoff[128];
__device__ int g_csrc[ET];                                   // CSR: src ids grouped by dst

// ---------------- K1: xl = x @ W^T  (tiled fp32 GEMM) ----------------
#define BM 64
#define BN 64
#define BK 16
__global__ void k_gemm(const float* __restrict__ A,
                       const float* __restrict__ Wm) {
    __shared__ float As[BK][BM];
    __shared__ float Bs[BK][BN];
    const int bm = blockIdx.y * BM;
    const int bn = blockIdx.x * BN;
    const int tid = threadIdx.x;            // 256 threads
    const int tx = tid & 15;
    const int ty = tid >> 4;

    float acc[4][4] = {};

    for (int kk = 0; kk < IN_CH; kk += BK) {
        #pragma unroll
        for (int i = tid; i < BM * BK; i += 256) {
            int m = i / BK, k = i % BK;
            int row = bm + m;
            As[k][m] = (row < N_NODES) ? A[(size_t)row * IN_CH + kk + k] : 0.f;
        }
        #pragma unroll
        for (int i = tid; i < BN * BK; i += 256) {
            int n = i / BK, k = i % BK;
            Bs[k][n] = Wm[(size_t)(bn + n) * IN_CH + kk + k];
        }
        __syncthreads();

        #pragma unroll
        for (int k = 0; k < BK; k++) {
            float a[4], b[4];
            #pragma unroll
            for (int i = 0; i < 4; i++) a[i] = As[k][ty * 4 + i];
            #pragma unroll
            for (int j = 0; j < 4; j++) b[j] = Bs[k][tx * 4 + j];
            #pragma unroll
            for (int i = 0; i < 4; i++)
                #pragma unroll
                for (int j = 0; j < 4; j++)
                    acc[i][j] += a[i] * b[j];
        }
        __syncthreads();
    }

    #pragma unroll
    for (int i = 0; i < 4; i++) {
        int row = bm + ty * 4 + i;
        if (row >= N_NODES) continue;
        #pragma unroll
        for (int j = 0; j < 4; j++)
            g_xl[(size_t)row * HC + bn + tx * 4 + j] = acc[i][j];
    }
}

// ---------------- K2: per-node attention logits ----------------
__global__ void k_logits(const float* __restrict__ att_src,
                         const float* __restrict__ att_dst) {
    int warp = (blockIdx.x * blockDim.x + threadIdx.x) >> 5;
    int lane = threadIdx.x & 31;
    if (warp >= N_NODES) return;
    int col = lane * 8;
    int h = lane >> 3;
    const float* xr = g_xl + (size_t)warp * HC + col;
    float ss = 0.f, sd = 0.f;
    #pragma unroll
    for (int j = 0; j < 8; j++) {
        float v = xr[j];
        ss += v * att_src[col + j];
        sd += v * att_dst[col + j];
    }
    #pragma unroll
    for (int off = 4; off >= 1; off >>= 1) {
        ss += __shfl_down_sync(0xffffffff, ss, off);
        sd += __shfl_down_sync(0xffffffff, sd, off);
    }
    if ((lane & 7) == 0) {
        g_asrc[warp * HEADS + h] = ss;
        g_adst[warp * HEADS + h] = sd;
    }
}

// ---------------- CSR build ----------------
__global__ void k_zero_deg() {
    int i = blockIdx.x * blockDim.x + threadIdx.x;
    if (i < N_NODES) g_deg[i] = 0;
}

__global__ void k_hist(const int* __restrict__ ei) {
    int e = blockIdx.x * blockDim.x + threadIdx.x;
    if (e >= ET) return;
    int d = (e < N_EDGES) ? ei[N_EDGES + e] : (e - N_EDGES);
    atomicAdd(&g_deg[d], 1);
}

// block-level inclusive scan (Hillis-Steele) over 512 elems
__global__ void k_scan1() {
    __shared__ int sh[512];
    int t = threadIdx.x;
    int i = blockIdx.x * 512 + t;
    int v = (i < N_NODES) ? g_deg[i] : 0;
    sh[t] = v;
    __syncthreads();
    #pragma unroll
    for (int off = 1; off < 512; off <<= 1) {
        int x = (t >= off) ? sh[t - off] : 0;
        __syncthreads();
        sh[t] += x;
        __syncthreads();
    }
    if (i < N_NODES) g_rowptr[i] = sh[t] - v;   // exclusive within block
    if (t == 511) g_blocksum[blockIdx.x] = sh[511];
}

__global__ void k_scan2() {
    __shared__ int sh[128];
    int t = threadIdx.x;
    int v = (t < NB_SCAN) ? g_blocksum[t] : 0;
    sh[t] = v;
    __syncthreads();
    #pragma unroll
    for (int off = 1; off < 128; off <<= 1) {
        int x = (t >= off) ? sh[t - off] : 0;
        __syncthreads();
        sh[t] += x;
        __syncthreads();
    }
    if (t < NB_SCAN) g_blockoff[t] = sh[t] - v;  // exclusive
}

__global__ void k_scan3() {
    int i = blockIdx.x * 512 + threadIdx.x;
    if (i < N_NODES) {
        int r = g_rowptr[i] + g_blockoff[blockIdx.x];
        g_rowptr[i] = r;
        g_cursor[i] = r;
    }
    if (i == 0) g_rowptr[N_NODES] = ET;
}

__global__ void k_fill(const int* __restrict__ ei) {
    int e = blockIdx.x * blockDim.x + threadIdx.x;
    if (e >= ET) return;
    int s, d;
    if (e < N_EDGES) { s = ei[e]; d = ei[N_EDGES + e]; }
    else             { s = d = e - N_EDGES; }
    int pos = atomicAdd(&g_cursor[d], 1);
    g_csrc[pos] = s;
}

// ---------------- K_agg: per-node softmax + weighted aggregate + bias + ELU ---
// one warp per dst node; lane l handles channels [8l, 8l+8), head = l/8
__global__ void k_node_agg(float* __restrict__ out,
                           const float* __restrict__ bias) {
    int n = (blockIdx.x * blockDim.x + threadIdx.x) >> 5;
    int lane = threadIdx.x & 31;
    if (n >= N_NODES) return;
    int h = lane >> 3;

    float ad = g_adst[n * 4 + h];
    int beg = g_rowptr[n];
    int end = g_rowptr[n + 1];

    float denom = 0.f;
    float acc[8] = {};

    for (int p = beg; p < end; p++) {
        int s = g_csrc[p];                    // broadcast load
        float a = g_asrc[s * 4 + h] + ad;
        a = (a > 0.f) ? a : NEG_SLOPE * a;    // leaky relu
        float e = __expf(a);                  // shift-invariant softmax: no max pass
        denom += e;
        const float4* xs = (const float4*)(g_xl + (size_t)s * HC) + lane * 2;
        float4 v0 = xs[0];
        float4 v1 = xs[1];
        acc[0] += e * v0.x; acc[1] += e * v0.y; acc[2] += e * v0.z; acc[3] += e * v0.w;
        acc[4] += e * v1.x; acc[5] += e * v1.y; acc[6] += e * v1.z; acc[7] += e * v1.w;
    }

    float inv = 1.f / denom;                  // every node has a self loop -> denom > 0
    const float4* bp = (const float4*)(bias) + lane * 2;
    float4 b0 = bp[0];
    float4 b1 = bp[1];
    float o[8];
    o[0] = acc[0] * inv + b0.x; o[1] = acc[1] * inv + b0.y;
    o[2] = acc[2] * inv + b0.z; o[3] = acc[3] * inv + b0.w;
    o[4] = acc[4] * inv + b1.x; o[5] = acc[5] * inv + b1.y;
    o[6] = acc[6] * inv + b1.z; o[7] = acc[7] * inv + b1.w;
    #pragma unroll
    for (int j = 0; j < 8; j++)
        o[j] = (o[j] > 0.f) ? o[j] : (expf(o[j]) - 1.f);   // ELU

    float4* op = (float4*)(out + (size_t)n * HC) + lane * 2;
    op[0] = make_float4(o[0], o[1], o[2], o[3]);
    op[1] = make_float4(o[4], o[5], o[6], o[7]);
}

// ---------------- launch ----------------
extern "C" void kernel_launch(void* const* d_in, const int* in_sizes, int n_in,
                              void* d_out, int out_size) {
    const float* x       = (const float*)d_in[0];
    const int*   ei      = (const int*)d_in[1];
    const float* Wm      = (const float*)d_in[2];
    const float* att_src = (const float*)d_in[3];
    const float* att_dst = (const float*)d_in[4];
    const float* bias    = (const float*)d_in[5];
    float*       out     = (float*)d_out;

    // projection GEMM
    dim3 ggrid(HC / BN, (N_NODES + BM - 1) / BM);
    k_gemm<<<ggrid, 256>>>(x, Wm);

    // per-node logits
    k_logits<<<(N_NODES * 32 + 255) / 256, 256>>>(att_src, att_dst);

    // CSR build (by destination)
    k_zero_deg<<<(N_NODES + 1023) / 1024, 1024>>>();
    k_hist<<<(ET + 255) / 256, 256>>>(ei);
    k_scan1<<<NB_SCAN, 512>>>();
    k_scan2<<<1, 128>>>();
    k_scan3<<<NB_SCAN, 512>>>();
    k_fill<<<(ET + 255) / 256, 256>>>(ei);

    // fused softmax + aggregate + bias + ELU (no atomics, registers only)
    k_node_agg<<<(N_NODES * 32 + 255) / 256, 256>>>(out, bias);
}

// round 8
// speedup vs baseline: 2.5038x; 1.4026x over previous
#include <cuda_runtime.h>

// ---------------- problem constants ----------------
#define N_NODES 50000
#define N_EDGES 800000
#define ET      (N_EDGES + N_NODES)   // edges + self loops
#define IN_CH   128
#define HEADS   4
#define C_CH    64
#define HC      256                    // HEADS * C_CH
#define NEG_SLOPE 0.2f
#define NB_SCAN 98                     // ceil(50000/512)

// ---------------- device scratch (device-side refs only) ----------------
__device__ __align__(16) float g_xl[(size_t)N_NODES * HC];   // projected features
__device__ __align__(16) float g_asrc[N_NODES * HEADS];
__device__ __align__(16) float g_adst[N_NODES * HEADS];
__device__ int g_deg[N_NODES];
__device__ int g_rowptr[N_NODES + 1];
__device__ int g_cursor[N_NODES];
__device__ int g_blocksum[128];
__device__ int g_blockoff[128];
__device__ int g_csrc[ET];                                   // CSR: src ids grouped by dst

// ---------------- K1: xl = x @ W^T  (128x128 tile, 8x8 microtile SGEMM) ------
#define BM 128
#define BN 128
#define BK 16
#define PAD 4
#define LDS_ROW (BM + PAD)            // padded smem row (132) kills xpose conflicts

__global__ __launch_bounds__(256, 2)
void k_gemm(const float* __restrict__ A,
            const float* __restrict__ Wm) {
    __shared__ float As[BK][LDS_ROW];
    __shared__ float Bs[BK][LDS_ROW];

    const int bm = blockIdx.y * BM;
    const int bn = blockIdx.x * BN;
    const int tid = threadIdx.x;       // 256 threads
    const int tx = tid & 15;           // 0..15 -> 8 cols each
    const int ty = tid >> 4;           // 0..15 -> 8 rows each

    float acc[8][8] = {};

    for (int kk = 0; kk < IN_CH; kk += BK) {
        // load A tile: rows [bm, bm+128), cols [kk, kk+16). 128x16 = 512 float4.
        #pragma unroll
        for (int i = 0; i < 2; i++) {
            int f    = tid + 256 * i;          // float4 index
            int row  = f >> 2;                 // 4 float4 per row
            int cseg = (f & 3) << 2;           // 0,4,8,12
            int grow = bm + row;
            float4 v = (grow < N_NODES)
                ? *(const float4*)(A + (size_t)grow * IN_CH + kk + cseg)
                : make_float4(0.f, 0.f, 0.f, 0.f);
            As[cseg + 0][row] = v.x;
            As[cseg + 1][row] = v.y;
            As[cseg + 2][row] = v.z;
            As[cseg + 3][row] = v.w;
        }
        // load B tile: W rows [bn, bn+128) (N dim), cols [kk, kk+16)
        #pragma unroll
        for (int i = 0; i < 2; i++) {
            int f    = tid + 256 * i;
            int row  = f >> 2;
            int cseg = (f & 3) << 2;
            float4 v = *(const float4*)(Wm + (size_t)(bn + row) * IN_CH + kk + cseg);
            Bs[cseg + 0][row] = v.x;
            Bs[cseg + 1][row] = v.y;
            Bs[cseg + 2][row] = v.z;
            Bs[cseg + 3][row] = v.w;
        }
        __syncthreads();

        #pragma unroll
        for (int k = 0; k < BK; k++) {
            float a[8], b[8];
            *(float4*)(a + 0) = *(const float4*)(&As[k][ty * 8 + 0]);
            *(float4*)(a + 4) = *(const float4*)(&As[k][ty * 8 + 4]);
            *(float4*)(b + 0) = *(const float4*)(&Bs[k][tx * 8 + 0]);
            *(float4*)(b + 4) = *(const float4*)(&Bs[k][tx * 8 + 4]);
            #pragma unroll
            for (int i = 0; i < 8; i++)
                #pragma unroll
                for (int j = 0; j < 8; j++)
                    acc[i][j] += a[i] * b[j];
        }
        __syncthreads();
    }

    #pragma unroll
    for (int i = 0; i < 8; i++) {
        int row = bm + ty * 8 + i;
        if (row >= N_NODES) continue;
        float* orow = g_xl + (size_t)row * HC + bn + tx * 8;
        *(float4*)(orow + 0) = make_float4(acc[i][0], acc[i][1], acc[i][2], acc[i][3]);
        *(float4*)(orow + 4) = make_float4(acc[i][4], acc[i][5], acc[i][6], acc[i][7]);
    }
}

// ---------------- K2: per-node attention logits ----------------
__global__ void k_logits(const float* __restrict__ att_src,
                         const float* __restrict__ att_dst) {
    int warp = (blockIdx.x * blockDim.x + threadIdx.x) >> 5;
    int lane = threadIdx.x & 31;
    if (warp >= N_NODES) return;
    int col = lane * 8;
    int h = lane >> 3;
    const float* xr = g_xl + (size_t)warp * HC + col;
    float ss = 0.f, sd = 0.f;
    #pragma unroll
    for (int j = 0; j < 8; j++) {
        float v = xr[j];
        ss += v * att_src[col + j];
        sd += v * att_dst[col + j];
    }
    #pragma unroll
    for (int off = 4; off >= 1; off >>= 1) {
        ss += __shfl_down_sync(0xffffffff, ss, off);
        sd += __shfl_down_sync(0xffffffff, sd, off);
    }
    if ((lane & 7) == 0) {
        g_asrc[warp * HEADS + h] = ss;
        g_adst[warp * HEADS + h] = sd;
    }
}

// ---------------- CSR build ----------------
__global__ void k_zero_deg() {
    int i = blockIdx.x * blockDim.x + threadIdx.x;
    if (i < N_NODES) g_deg[i] = 0;
}

__global__ void k_hist(const int* __restrict__ ei) {
    int e = blockIdx.x * blockDim.x + threadIdx.x;
    if (e >= ET) return;
    int d = (e < N_EDGES) ? ei[N_EDGES + e] : (e - N_EDGES);
    atomicAdd(&g_deg[d], 1);
}

__global__ void k_scan1() {
    __shared__ int sh[512];
    int t = threadIdx.x;
    int i = blockIdx.x * 512 + t;
    int v = (i < N_NODES) ? g_deg[i] : 0;
    sh[t] = v;
    __syncthreads();
    #pragma unroll
    for (int off = 1; off < 512; off <<= 1) {
        int x = (t >= off) ? sh[t - off] : 0;
        __syncthreads();
        sh[t] += x;
        __syncthreads();
    }
    if (i < N_NODES) g_rowptr[i] = sh[t] - v;   // exclusive within block
    if (t == 511) g_blocksum[blockIdx.x] = sh[511];
}

__global__ void k_scan2() {
    __shared__ int sh[128];
    int t = threadIdx.x;
    int v = (t < NB_SCAN) ? g_blocksum[t] : 0;
    sh[t] = v;
    __syncthreads();
    #pragma unroll
    for (int off = 1; off < 128; off <<= 1) {
        int x = (t >= off) ? sh[t - off] : 0;
        __syncthreads();
        sh[t] += x;
        __syncthreads();
    }
    if (t < NB_SCAN) g_blockoff[t] = sh[t] - v;  // exclusive
}

__global__ void k_scan3() {
    int i = blockIdx.x * 512 + threadIdx.x;
    if (i < N_NODES) {
        int r = g_rowptr[i] + g_blockoff[blockIdx.x];
        g_rowptr[i] = r;
        g_cursor[i] = r;
    }
    if (i == 0) g_rowptr[N_NODES] = ET;
}

__global__ void k_fill(const int* __restrict__ ei) {
    int e = blockIdx.x * blockDim.x + threadIdx.x;
    if (e >= ET) return;
    int s, d;
    if (e < N_EDGES) { s = ei[e]; d = ei[N_EDGES + e]; }
    else             { s = d = e - N_EDGES; }
    int pos = atomicAdd(&g_cursor[d], 1);
    g_csrc[pos] = s;
}

// ---------------- K_agg: per-node softmax + weighted aggregate + bias + ELU ---
__global__ void k_node_agg(float* __restrict__ out,
                           const float* __restrict__ bias) {
    int n = (blockIdx.x * blockDim.x + threadIdx.x) >> 5;
    int lane = threadIdx.x & 31;
    if (n >= N_NODES) return;
    int h = lane >> 3;

    float ad = g_adst[n * 4 + h];
    int beg = g_rowptr[n];
    int end = g_rowptr[n + 1];

    float denom = 0.f;
    float acc[8] = {};

    for (int p = beg; p < end; p++) {
        int s = g_csrc[p];                    // broadcast load
        float a = g_asrc[s * 4 + h] + ad;
        a = (a > 0.f) ? a : NEG_SLOPE * a;    // leaky relu
        float e = __expf(a);                  // shift-invariant softmax: no max pass
        denom += e;
        const float4* xs = (const float4*)(g_xl + (size_t)s * HC) + lane * 2;
        float4 v0 = xs[0];
        float4 v1 = xs[1];
        acc[0] += e * v0.x; acc[1] += e * v0.y; acc[2] += e * v0.z; acc[3] += e * v0.w;
        acc[4] += e * v1.x; acc[5] += e * v1.y; acc[6] += e * v1.z; acc[7] += e * v1.w;
    }

    float inv = 1.f / denom;
    const float4* bp = (const float4*)(bias) + lane * 2;
    float4 b0 = bp[0];
    float4 b1 = bp[1];
    float o[8];
    o[0] = acc[0] * inv + b0.x; o[1] = acc[1] * inv + b0.y;
    o[2] = acc[2] * inv + b0.z; o[3] = acc[3] * inv + b0.w;
    o[4] = acc[4] * inv + b1.x; o[5] = acc[5] * inv + b1.y;
    o[6] = acc[6] * inv + b1.z; o[7] = acc[7] * inv + b1.w;
    #pragma unroll
    for (int j = 0; j < 8; j++)
        o[j] = (o[j] > 0.f) ? o[j] : (expf(o[j]) - 1.f);   // ELU

    float4* op = (float4*)(out + (size_t)n * HC) + lane * 2;
    op[0] = make_float4(o[0], o[1], o[2], o[3]);
    op[1] = make_float4(o[4], o[5], o[6], o[7]);
}

// ---------------- launch ----------------
extern "C" void kernel_launch(void* const* d_in, const int* in_sizes, int n_in,
                              void* d_out, int out_size) {
    const float* x       = (const float*)d_in[0];
    const int*   ei      = (const int*)d_in[1];
    const float* Wm      = (const float*)d_in[2];
    const float* att_src = (const float*)d_in[3];
    const float* att_dst = (const float*)d_in[4];
    const float* bias    = (const float*)d_in[5];
    float*       out     = (float*)d_out;

    // projection GEMM (128x128 tiles, 8x8 microtile)
    dim3 ggrid(HC / BN, (N_NODES + BM - 1) / BM);
    k_gemm<<<ggrid, 256>>>(x, Wm);

    // per-node logits
    k_logits<<<(N_NODES * 32 + 255) / 256, 256>>>(att_src, att_dst);

    // CSR build (by destination)
    k_zero_deg<<<(N_NODES + 1023) / 1024, 1024>>>();
    k_hist<<<(ET + 255) / 256, 256>>>(ei);
    k_scan1<<<NB_SCAN, 512>>>();
    k_scan2<<<1, 128>>>();
    k_scan3<<<NB_SCAN, 512>>>();
    k_fill<<<(ET + 255) / 256, 256>>>(ei);

    // fused softmax + aggregate + bias + ELU
    k_node_agg<<<(N_NODES * 32 + 255) / 256, 256>>>(out, bias);
}

// round 10
// speedup vs baseline: 3.3569x; 1.3407x over previous
#include <cuda_runtime.h>
#include <cuda_fp16.h>

// ---------------- problem constants ----------------
#define N_NODES 50000
#define N_EDGES 800000
#define ET      (N_EDGES + N_NODES)   // edges + self loops
#define IN_CH   128
#define HEADS   4
#define C_CH    64
#define HC      256                    // HEADS * C_CH
#define NEG_SLOPE 0.2f
#define NB_SCAN 98                     // ceil(50000/512)

// ---------------- device scratch (device-side refs only) ----------------
__device__ __align__(16) __half g_xlh[(size_t)N_NODES * HC]; // fp16 projected features
__device__ __align__(16) float g_asrc[N_NODES * HEADS];
__device__ __align__(16) float g_adst[N_NODES * HEADS];
__device__ int g_deg[N_NODES];
__device__ int g_rowptr[N_NODES + 1];
__device__ int g_cursor[N_NODES];
__device__ int g_blocksum[128];
__device__ int g_blockoff[128];
__device__ int g_csrc[ET];                                   // CSR: src ids grouped by dst

// ---------------- K1: xl = x @ W^T  + fused logits epilogue ------------------
// 128x128 tile, 8x8 microtile. Features stored fp16; logits computed from the
// fp32 accumulators in-epilogue (each head's 64 channels live inside one block
// and one 8-lane tx-group -> one shuffle reduce gives the full head dot).
#define BM 128
#define BN 128
#define BK 16
#define PAD 4
#define LDS_ROW (BM + PAD)

__global__ __launch_bounds__(256, 2)
void k_gemm(const float* __restrict__ A,
            const float* __restrict__ Wm,
            const float* __restrict__ att_src,
            const float* __restrict__ att_dst) {
    __shared__ float As[BK][LDS_ROW];
    __shared__ float Bs[BK][LDS_ROW];

    const int bm = blockIdx.y * BM;
    const int bn = blockIdx.x * BN;
    const int tid = threadIdx.x;       // 256 threads
    const int tx = tid & 15;           // 0..15 -> 8 cols each
    const int ty = tid >> 4;           // 0..15 -> 8 rows each

    float acc[8][8] = {};

    for (int kk = 0; kk < IN_CH; kk += BK) {
        #pragma unroll
        for (int i = 0; i < 2; i++) {
            int f    = tid + 256 * i;          // float4 index
            int row  = f >> 2;
            int cseg = (f & 3) << 2;
            int grow = bm + row;
            float4 v = (grow < N_NODES)
                ? *(const float4*)(A + (size_t)grow * IN_CH + kk + cseg)
                : make_float4(0.f, 0.f, 0.f, 0.f);
            As[cseg + 0][row] = v.x;
            As[cseg + 1][row] = v.y;
            As[cseg + 2][row] = v.z;
            As[cseg + 3][row] = v.w;
        }
        #pragma unroll
        for (int i = 0; i < 2; i++) {
            int f    = tid + 256 * i;
            int row  = f >> 2;
            int cseg = (f & 3) << 2;
            float4 v = *(const float4*)(Wm + (size_t)(bn + row) * IN_CH + kk + cseg);
            Bs[cseg + 0][row] = v.x;
            Bs[cseg + 1][row] = v.y;
            Bs[cseg + 2][row] = v.z;
            Bs[cseg + 3][row] = v.w;
        }
        __syncthreads();

        #pragma unroll
        for (int k = 0; k < BK; k++) {
            float a[8], b[8];
            *(float4*)(a + 0) = *(const float4*)(&As[k][ty * 8 + 0]);
            *(float4*)(a + 4) = *(const float4*)(&As[k][ty * 8 + 4]);
            *(float4*)(b + 0) = *(const float4*)(&Bs[k][tx * 8 + 0]);
            *(float4*)(b + 4) = *(const float4*)(&Bs[k][tx * 8 + 4]);
            #pragma unroll
            for (int i = 0; i < 8; i++)
                #pragma unroll
                for (int j = 0; j < 8; j++)
                    acc[i][j] += a[i] * b[j];
        }
        __syncthreads();
    }

    // attention weight slices for this thread's 8 channels
    float ats[8], atd[8];
    #pragma unroll
    for (int j = 0; j < 8; j++) {
        ats[j] = __ldg(att_src + bn + tx * 8 + j);
        atd[j] = __ldg(att_dst + bn + tx * 8 + j);
    }
    const int head = (bn >> 6) + (tx >> 3);   // this 8-lane group's head

    #pragma unroll
    for (int i = 0; i < 8; i++) {
        int row = bm + ty * 8 + i;
        bool valid = (row < N_NODES);

        // fp16 feature store (16B per thread-row)
        if (valid) {
            __half2 h[4];
            h[0] = __floats2half2_rn(acc[i][0], acc[i][1]);
            h[1] = __floats2half2_rn(acc[i][2], acc[i][3]);
            h[2] = __floats2half2_rn(acc[i][4], acc[i][5]);
            h[3] = __floats2half2_rn(acc[i][6], acc[i][7]);
            *(uint2*)(g_xlh + (size_t)row * HC + bn + tx * 8) = *(uint2*)h;
            *(uint2*)(g_xlh + (size_t)row * HC + bn + tx * 8 + 4) = *(uint2*)(h + 2);
        }

        // fused logit partial: this thread's 8-channel dot, reduce over 8 lanes
        float ps = 0.f, pd = 0.f;
        #pragma unroll
        for (int j = 0; j < 8; j++) {
            ps += acc[i][j] * ats[j];
            pd += acc[i][j] * atd[j];
        }
        #pragma unroll
        for (int off = 4; off >= 1; off >>= 1) {
            ps += __shfl_down_sync(0xffffffff, ps, off);
            pd += __shfl_down_sync(0xffffffff, pd, off);
        }
        if (valid && (tx & 7) == 0) {
            g_asrc[row * 4 + head] = ps;   // full 64-ch head dot, no atomics
            g_adst[row * 4 + head] = pd;
        }
    }
}

// ---------------- CSR build ----------------
__global__ void k_zero_deg() {
    int i = blockIdx.x * blockDim.x + threadIdx.x;
    if (i < N_NODES) g_deg[i] = 0;
}

__global__ void k_hist(const int* __restrict__ ei) {
    int e = blockIdx.x * blockDim.x + threadIdx.x;
    if (e >= ET) return;
    int d = (e < N_EDGES) ? ei[N_EDGES + e] : (e - N_EDGES);
    atomicAdd(&g_deg[d], 1);
}

__global__ void k_scan1() {
    __shared__ int sh[512];
    int t = threadIdx.x;
    int i = blockIdx.x * 512 + t;
    int v = (i < N_NODES) ? g_deg[i] : 0;
    sh[t] = v;
    __syncthreads();
    #pragma unroll
    for (int off = 1; off < 512; off <<= 1) {
        int x = (t >= off) ? sh[t - off] : 0;
        __syncthreads();
        sh[t] += x;
        __syncthreads();
    }
    if (i < N_NODES) g_rowptr[i] = sh[t] - v;   // exclusive within block
    if (t == 511) g_blocksum[blockIdx.x] = sh[511];
}

__global__ void k_scan2() {
    __shared__ int sh[128];
    int t = threadIdx.x;
    int v = (t < NB_SCAN) ? g_blocksum[t] : 0;
    sh[t] = v;
    __syncthreads();
    #pragma unroll
    for (int off = 1; off < 128; off <<= 1) {
        int x = (t >= off) ? sh[t - off] : 0;
        __syncthreads();
        sh[t] += x;
        __syncthreads();
    }
    if (t < NB_SCAN) g_blockoff[t] = sh[t] - v;  // exclusive
}

__global__ void k_scan3() {
    int i = blockIdx.x * 512 + threadIdx.x;
    if (i < N_NODES) {
        int r = g_rowptr[i] + g_blockoff[blockIdx.x];
        g_rowptr[i] = r;
        g_cursor[i] = r;
    }
    if (i == 0) g_rowptr[N_NODES] = ET;
}

__global__ void k_fill(const int* __restrict__ ei) {
    int e = blockIdx.x * blockDim.x + threadIdx.x;
    if (e >= ET) return;
    int s, d;
    if (e < N_EDGES) { s = ei[e]; d = ei[N_EDGES + e]; }
    else             { s = d = e - N_EDGES; }
    int pos = atomicAdd(&g_cursor[d], 1);
    g_csrc[pos] = s;
}

// ---------------- K_agg: per-node softmax + weighted aggregate + bias + ELU ---
// one warp per dst node; lane l handles channels [8l, 8l+8) (16B fp16), head = l/8
__global__ void k_node_agg(float* __restrict__ out,
                           const float* __restrict__ bias) {
    int n = (blockIdx.x * blockDim.x + threadIdx.x) >> 5;
    int lane = threadIdx.x & 31;
    if (n >= N_NODES) return;
    int h = lane >> 3;

    float ad = g_adst[n * 4 + h];
    int beg = g_rowptr[n];
    int end = g_rowptr[n + 1];

    float denom = 0.f;
    float acc[8] = {};

    for (int p = beg; p < end; p++) {
        int s = g_csrc[p];                    // broadcast load
        float a = g_asrc[s * 4 + h] + ad;
        a = (a > 0.f) ? a : NEG_SLOPE * a;    // leaky relu
        float e = __expf(a);                  // shift-invariant softmax: no max pass
        denom += e;
        uint4 raw = *((const uint4*)(g_xlh + (size_t)s * HC) + lane);  // 8 halves
        const __half2* hp = (const __half2*)&raw;
        float2 f0 = __half22float2(hp[0]);
        float2 f1 = __half22float2(hp[1]);
        float2 f2 = __half22float2(hp[2]);
        float2 f3 = __half22float2(hp[3]);
        acc[0] += e * f0.x; acc[1] += e * f0.y;
        acc[2] += e * f1.x; acc[3] += e * f1.y;
        acc[4] += e * f2.x; acc[5] += e * f2.y;
        acc[6] += e * f3.x; acc[7] += e * f3.y;
    }

    float inv = 1.f / denom;                  // self loop guarantees denom > 0
    const float4* bp = (const float4*)(bias) + lane * 2;
    float4 b0 = bp[0];
    float4 b1 = bp[1];
    float o[8];
    o[0] = acc[0] * inv + b0.x; o[1] = acc[1] * inv + b0.y;
    o[2] = acc[2] * inv + b0.z; o[3] = acc[3] * inv + b0.w;
    o[4] = acc[4] * inv + b1.x; o[5] = acc[5] * inv + b1.y;
    o[6] = acc[6] * inv + b1.z; o[7] = acc[7] * inv + b1.w;
    #pragma unroll
    for (int j = 0; j < 8; j++)
        o[j] = (o[j] > 0.f) ? o[j] : (expf(o[j]) - 1.f);   // ELU

    float4* op = (float4*)(out + (size_t)n * HC) + lane * 2;
    op[0] = make_float4(o[0], o[1], o[2], o[3]);
    op[1] = make_float4(o[4], o[5], o[6], o[7]);
}

// ---------------- launch ----------------
extern "C" void kernel_launch(void* const* d_in, const int* in_sizes, int n_in,
                              void* d_out, int out_size) {
    const float* x       = (const float*)d_in[0];
    const int*   ei      = (const int*)d_in[1];
    const float* Wm      = (const float*)d_in[2];
    const float* att_src = (const float*)d_in[3];
    const float* att_dst = (const float*)d_in[4];
    const float* bias    = (const float*)d_in[5];
    float*       out     = (float*)d_out;

    // projection GEMM + fused logits + fp16 feature store
    dim3 ggrid(HC / BN, (N_NODES + BM - 1) / BM);
    k_gemm<<<ggrid, 256>>>(x, Wm, att_src, att_dst);

    // CSR build (by destination)
    k_zero_deg<<<(N_NODES + 1023) / 1024, 1024>>>();
    k_hist<<<(ET + 255) / 256, 256>>>(ei);
    k_scan1<<<NB_SCAN, 512>>>();
    k_scan2<<<1, 128>>>();
    k_scan3<<<NB_SCAN, 512>>>();
    k_fill<<<(ET + 255) / 256, 256>>>(ei);

    // fused softmax + aggregate + bias + ELU
    k_node_agg<<<(N_NODES * 32 + 255) / 256, 256>>>(out, bias);
}